// round 14
// baseline (speedup 1.0000x reference)
#include <cuda_runtime.h>
#include <cuda_fp16.h>
#include <math.h>
#include <stdint.h>

#define B   2
#define T   2048
#define D   1024
#define NH  16
#define NKV 4
#define HD  64
#define GQ  4            // NH / NKV
#define EPSF 1.1920929e-07f
#define LOG2E 1.4426950408889634f
#define PSTR 12          // GEMM smem word stride (8 data + 4 pad) -> conflict-free frags
#define KSTR 48          // attn K plane stride: 48 mod 32 = 16 -> conflict-free LDS.128
#define VSTR 68          // attn V plane stride: 68 mod 32 = 4  -> near-conflict-free LDS.128

// ---------------- scratch (no allocations allowed) ----------------
__device__ float    g_q[B*T*NH*HD];        // q projection (fp32)
__device__ float    g_k[B*T*NKV*HD];       // k projection (fp32)
__device__ float    g_y[B*T*NH*HD];        // attention output (gate folded in)
__device__ float    g_gate[B*T*NH];        // sigmoid gate
__device__ uint32_t g_qh[B*T*NH*(HD/2)];   // q normed/roped/gained: fp16x2 (unpermuted)
__device__ uint32_t g_kh[B*T*NKV*(HD/2)];  // k hi plane   (PERMUTED: word w at (w&7)*4+(w>>3))
__device__ uint32_t g_km[B*T*NKV*(HD/2)];  // k mid plane  (same permute)
__device__ uint32_t g_vth[B*NKV*(T/2)*HD]; // v hi plane [b][kv][t/2][pd], pd=(d&7)*8+(d>>3)
__device__ uint32_t g_vtm[B*NKV*(T/2)*HD]; // v mid plane

// ---------------- mma helpers ----------------
__device__ __forceinline__ void mma_bf16(float* c, const uint32_t* a, const uint32_t* b) {
    asm volatile(
        "mma.sync.aligned.m16n8k16.row.col.f32.bf16.bf16.f32 "
        "{%0,%1,%2,%3}, {%4,%5,%6,%7}, {%8,%9}, {%0,%1,%2,%3};\n"
        : "+f"(c[0]), "+f"(c[1]), "+f"(c[2]), "+f"(c[3])
        : "r"(a[0]), "r"(a[1]), "r"(a[2]), "r"(a[3]), "r"(b[0]), "r"(b[1]));
}
__device__ __forceinline__ void mma_f16(float* c, const uint32_t* a, const uint32_t* b) {
    asm volatile(
        "mma.sync.aligned.m16n8k16.row.col.f32.f16.f16.f32 "
        "{%0,%1,%2,%3}, {%4,%5,%6,%7}, {%8,%9}, {%0,%1,%2,%3};\n"
        : "+f"(c[0]), "+f"(c[1]), "+f"(c[2]), "+f"(c[3])
        : "r"(a[0]), "r"(a[1]), "r"(a[2]), "r"(a[3]), "r"(b[0]), "r"(b[1]));
}

// bf16 split (GEMM path, proven)
__device__ __forceinline__ void split2_pack(float x0, float x1, uint32_t& wh, uint32_t& wm) {
    asm("cvt.rn.bf16x2.f32 %0, %1, %2;" : "=r"(wh) : "f"(x1), "f"(x0));
    float h0 = __uint_as_float(wh << 16);
    float h1 = __uint_as_float(wh & 0xffff0000u);
    asm("cvt.rn.bf16x2.f32 %0, %1, %2;" : "=r"(wm) : "f"(x1 - h1), "f"(x0 - h0));
}
// fp16 split (attention K/V path)
__device__ __forceinline__ void split2_pack_f16(float x0, float x1, uint32_t& wh, uint32_t& wm) {
    __half2 h = __floats2half2_rn(x0, x1);
    wh = *(uint32_t*)&h;
    float2 hf = __half22float2(h);
    __half2 m = __floats2half2_rn(x0 - hf.x, x1 - hf.y);
    wm = *(uint32_t*)&m;
}
// pack two fp32 softmax args, take 2 exponentials in ONE MUFU op
__device__ __forceinline__ uint32_t ex2_pair(float a0, float a1) {
    uint32_t w, r;
    asm("cvt.rn.satfinite.f16x2.f32 %0, %1, %2;" : "=r"(w) : "f"(a1), "f"(a0));
    asm("ex2.approx.f16x2 %0, %1;" : "=r"(r) : "r"(w));
    return r;
}

// ---------------- fused bf16-split GEMM ----------------
// job=0: QKV fused. grid.x: [0,8)=Q, [8,10)=K, [10,12)=V (v epilogue writes planes directly).
// job=1: O projection (A = g_y, C = out).
__global__ __launch_bounds__(256)
void gemm_bf16(const float* __restrict__ x,  const float* __restrict__ qw,
               const float* __restrict__ kw, const float* __restrict__ vw,
               const float* __restrict__ ow, const float* __restrict__ ve,
               const float* __restrict__ v0, const float* __restrict__ lam,
               float* __restrict__ out, float* __restrict__ raw_out, int job) {
    __shared__ uint32_t Ah[2][128*PSTR], Am[2][128*PSTR];
    __shared__ uint32_t Bh[2][128*PSTR], Bm[2][128*PSTR];

    const float* A; const float* W; float* C = nullptr; int N, n0; bool vjob = false;
    if (job == 0) {
        A = x;
        int bx = blockIdx.x;
        if (bx < 8)       { W = qw; C = g_q; N = NH*HD;  n0 = bx * 128; }
        else if (bx < 10) { W = kw; C = g_k; N = NKV*HD; n0 = (bx - 8) * 128; }
        else              { W = vw; C = nullptr; N = NKV*HD; n0 = (bx - 10) * 128; vjob = true; }
    } else {
        A = g_y; W = ow; C = out; N = D; n0 = blockIdx.x * 128;
    }
    const int K = D;
    const int m0 = blockIdx.y * 128;

    const int tid  = threadIdx.x;
    const int lane = tid & 31;
    const int w    = tid >> 5;
    const int wm   = w & 1;
    const int wn   = w >> 1;
    const int tq   = lane >> 2;
    const int tr   = lane & 3;

    const int lrow = tid >> 1;
    const int lc8  = (tid & 1) * 8;
    const int lw   = (tid & 1) * 4;

    const float* aN = A + (size_t)(m0 + lrow) * K + lc8;
    const float* bN = W + (size_t)(n0 + lrow) * K + lc8;

    float c[16][4];
    #pragma unroll
    for (int i = 0; i < 16; i++)
        #pragma unroll
        for (int j = 0; j < 4; j++) c[i][j] = 0.f;

    {
        float4 a0 = *(const float4*)(aN);
        float4 a1 = *(const float4*)(aN + 4);
        float4 b0 = *(const float4*)(bN);
        float4 b1 = *(const float4*)(bN + 4);
        uint32_t h[4], m[4];
        split2_pack(a0.x, a0.y, h[0], m[0]); split2_pack(a0.z, a0.w, h[1], m[1]);
        split2_pack(a1.x, a1.y, h[2], m[2]); split2_pack(a1.z, a1.w, h[3], m[3]);
        *(uint4*)&Ah[0][lrow*PSTR + lw] = make_uint4(h[0], h[1], h[2], h[3]);
        *(uint4*)&Am[0][lrow*PSTR + lw] = make_uint4(m[0], m[1], m[2], m[3]);
        split2_pack(b0.x, b0.y, h[0], m[0]); split2_pack(b0.z, b0.w, h[1], m[1]);
        split2_pack(b1.x, b1.y, h[2], m[2]); split2_pack(b1.z, b1.w, h[3], m[3]);
        *(uint4*)&Bh[0][lrow*PSTR + lw] = make_uint4(h[0], h[1], h[2], h[3]);
        *(uint4*)&Bm[0][lrow*PSTR + lw] = make_uint4(m[0], m[1], m[2], m[3]);
    }
    __syncthreads();

    const int niter = K / 16;
    int cur = 0;
    for (int it = 0; it < niter; it++) {
        float4 pa0, pa1, pb0, pb1;
        const bool has_next = (it + 1 < niter);
        if (has_next) {
            int k0 = (it + 1) * 16;
            pa0 = *(const float4*)(aN + k0);
            pa1 = *(const float4*)(aN + k0 + 4);
            pb0 = *(const float4*)(bN + k0);
            pb1 = *(const float4*)(bN + k0 + 4);
        }

        const uint32_t* ah = Ah[cur]; const uint32_t* am = Am[cur];
        const uint32_t* bh = Bh[cur]; const uint32_t* bm = Bm[cur];

        uint32_t afh[4][4], afm[4][4], bfh[4][2], bfm[4][2];
        #pragma unroll
        for (int mi = 0; mi < 4; mi++) {
            int r = wm * 64 + mi * 16 + tq;
            afh[mi][0] = ah[r*PSTR + tr];     afh[mi][1] = ah[(r+8)*PSTR + tr];
            afh[mi][2] = ah[r*PSTR + tr + 4]; afh[mi][3] = ah[(r+8)*PSTR + tr + 4];
            afm[mi][0] = am[r*PSTR + tr];     afm[mi][1] = am[(r+8)*PSTR + tr];
            afm[mi][2] = am[r*PSTR + tr + 4]; afm[mi][3] = am[(r+8)*PSTR + tr + 4];
        }
        #pragma unroll
        for (int ni = 0; ni < 4; ni++) {
            int rn = wn * 32 + ni * 8 + tq;
            bfh[ni][0] = bh[rn*PSTR + tr]; bfh[ni][1] = bh[rn*PSTR + tr + 4];
            bfm[ni][0] = bm[rn*PSTR + tr]; bfm[ni][1] = bm[rn*PSTR + tr + 4];
        }
        #pragma unroll
        for (int mi = 0; mi < 4; mi++)
            #pragma unroll
            for (int ni = 0; ni < 4; ni++) {
                mma_bf16(c[mi*4+ni], afh[mi], bfh[ni]);
                mma_bf16(c[mi*4+ni], afh[mi], bfm[ni]);
                mma_bf16(c[mi*4+ni], afm[mi], bfh[ni]);
            }

        if (has_next) {
            int nxt = cur ^ 1;
            uint32_t h[4], m[4];
            split2_pack(pa0.x, pa0.y, h[0], m[0]); split2_pack(pa0.z, pa0.w, h[1], m[1]);
            split2_pack(pa1.x, pa1.y, h[2], m[2]); split2_pack(pa1.z, pa1.w, h[3], m[3]);
            *(uint4*)&Ah[nxt][lrow*PSTR + lw] = make_uint4(h[0], h[1], h[2], h[3]);
            *(uint4*)&Am[nxt][lrow*PSTR + lw] = make_uint4(m[0], m[1], m[2], m[3]);
            split2_pack(pb0.x, pb0.y, h[0], m[0]); split2_pack(pb0.z, pb0.w, h[1], m[1]);
            split2_pack(pb1.x, pb1.y, h[2], m[2]); split2_pack(pb1.z, pb1.w, h[3], m[3]);
            *(uint4*)&Bh[nxt][lrow*PSTR + lw] = make_uint4(h[0], h[1], h[2], h[3]);
            *(uint4*)&Bm[nxt][lrow*PSTR + lw] = make_uint4(m[0], m[1], m[2], m[3]);
            __syncthreads();
            cur = nxt;
        }
    }

    if (!vjob) {
        #pragma unroll
        for (int mi = 0; mi < 4; mi++)
            #pragma unroll
            for (int ni = 0; ni < 4; ni++) {
                int row = m0 + wm*64 + mi*16 + tq;
                int col = n0 + wn*32 + ni*8 + 2*tr;
                float* cp = c[mi*4+ni];
                *(float2*)(C + (size_t)row * N + col)       = make_float2(cp[0], cp[1]);
                *(float2*)(C + (size_t)(row + 8) * N + col) = make_float2(cp[2], cp[3]);
            }
    } else {
        // V epilogue: raw_v out + lambda mix + DIRECT packed fp16 plane write (t-pairs via shfl)
        const float l0 = lam[0], l1 = lam[1];
        #pragma unroll
        for (int mi = 0; mi < 4; mi++)
            #pragma unroll
            for (int ni = 0; ni < 4; ni++) {
                int row = m0 + wm*64 + mi*16 + tq;
                int col = n0 + wn*32 + ni*8 + 2*tr;
                float* cp = c[mi*4+ni];
                #pragma unroll
                for (int half = 0; half < 2; half++) {
                    int rr = row + half*8;
                    size_t gi = (size_t)rr * N + col;
                    float2 vee = *(const float2*)(ve + gi);
                    float2 v00 = *(const float2*)(v0 + gi);
                    float r0 = cp[half*2]   + vee.x;
                    float r1 = cp[half*2+1] + vee.y;
                    *(float2*)(raw_out + gi) = make_float2(r0, r1);
                    float mv0 = l0*v00.x + l1*r0;
                    float mv1 = l0*v00.y + l1*r1;
                    float p0 = __shfl_xor_sync(0xffffffffu, mv0, 4);
                    float p1 = __shfl_xor_sync(0xffffffffu, mv1, 4);
                    if (!(tq & 1)) {   // even t: pack (self, partner)
                        int bb = rr >> 11, tt = rr & (T - 1);
                        int kvi = col >> 6, dd = col & 63;
                        size_t vb = ((size_t)(bb*NKV + kvi)*(T/2) + (tt >> 1)) * 64;
                        uint32_t wh, wmv;
                        split2_pack_f16(mv0, p0, wh, wmv);
                        g_vth[vb + (dd & 7)*8 + (dd >> 3)] = wh;
                        g_vtm[vb + (dd & 7)*8 + (dd >> 3)] = wmv;
                        split2_pack_f16(mv1, p1, wh, wmv);
                        int d1 = dd + 1;
                        g_vth[vb + (d1 & 7)*8 + (d1 >> 3)] = wh;
                        g_vtm[vb + (d1 & 7)*8 + (d1 >> 3)] = wmv;
                    }
                }
            }
    }
}

// ---------------- merged RMSNorm + RoPE (+gain) -> packed fp16x2 planes ----------------
// global rows [0, B*T*NH): Q (unpermuted layout); rest: K (permuted word layout).
__global__ void rmsnorm_rope_pack(const float* __restrict__ gain, double nb) {
    int grow = blockIdx.x * 8 + (threadIdx.x >> 5);
    int lane = threadIdx.x & 31;
    const bool isQ = grow < B*T*NH;
    int row = isQ ? grow : grow - B*T*NH;
    int H   = isQ ? NH : NKV;
    const float* src = isQ ? g_q : g_k;
    int t = (row / H) % T;
    int h = row % H;
    const float* p = src + (size_t)row * HD;

    float a  = p[lane];
    float b2 = p[lane + 32];
    float ss = a*a + b2*b2;
    #pragma unroll
    for (int o = 16; o; o >>= 1) ss += __shfl_xor_sync(0xffffffffu, ss, o);
    float r = rsqrtf(ss * (1.0f/HD) + EPSF);
    a *= r; b2 *= r;

    float inv = (float)pow(nb, -(double)(2*lane) / (double)HD);
    float fr  = (float)t * inv;
    float cc = (float)cos((double)fr);
    float sn = (float)sin((double)fr);

    float o1 =  a*cc + b2*sn;          // d = lane
    float o2 = -a*sn + b2*cc;          // d = lane + 32
    if (isQ) { float gg = gain[h]; o1 *= gg; o2 *= gg; }

    float p1 = __shfl_xor_sync(0xffffffffu, o1, 1);
    float p2 = __shfl_xor_sync(0xffffffffu, o2, 1);
    uint32_t wh, wmv; int widx;
    if (lane & 1) { split2_pack_f16(p2, o2, wh, wmv); widx = 16 + (lane >> 1); }
    else          { split2_pack_f16(o1, p1, wh, wmv); widx = lane >> 1; }
    if (isQ) {
        g_qh[(size_t)row * 32 + widx] = wh;
    } else {
        int pidx = (widx & 7)*4 + (widx >> 3);   // permute for LDS.128 fragments
        g_kh[(size_t)row * 32 + pidx] = wh;
        g_km[(size_t)row * 32 + pidx] = wmv;
    }
}

// ---------------- gate: sigmoid(x @ gate_w^T + gate_b), one block per (b,t) ----------------
__global__ void gate_kernel(const float* __restrict__ x, const float* __restrict__ gw,
                            const float* __restrict__ gb) {
    __shared__ float xs[D];
    int bt = blockIdx.x;
    for (int i = threadIdx.x; i < D; i += 512) xs[i] = x[(size_t)bt * D + i];
    __syncthreads();
    int h = threadIdx.x >> 5, lane = threadIdx.x & 31;
    const float* w = gw + (size_t)h * D;
    float s = 0.f;
    for (int i = lane; i < D; i += 32) s += xs[i] * w[i];
    #pragma unroll
    for (int o = 16; o; o >>= 1) s += __shfl_xor_sync(0xffffffffu, s, o);
    if (lane == 0) g_gate[bt * NH + h] = 1.0f / (1.0f + __expf(-(s + gb[h])));
}

// ---------------- fp16 flash attention: vector-LDS fragments (permuted planes) ----------------
__global__ __launch_bounds__(128)
void attn_f16() {
    __shared__ uint32_t Kh[64*KSTR], Km[64*KSTR];   // [key n][permuted word]
    __shared__ uint32_t Vh[32*VSTR], Vm[32*VSTR];   // [t-pair][permuted d]

    const int qt = (int)gridDim.x - 1 - (int)blockIdx.x;   // heavy tiles first
    const int h = blockIdx.y, b = blockIdx.z;
    const int kv = h / GQ;
    const int tid = threadIdx.x;
    const int w = tid >> 5, lane = tid & 31;
    const int tq = lane >> 2, tr = lane & 3;
    const int r0 = w * 16 + tq;

    // persistent Q fragments (fp16, unpermuted plane)
    uint32_t qh[4][4];
    {
        const size_t qA = ((size_t)(b*T + qt*64 + r0) * NH + h) * 32;
        const size_t qB = qA + (size_t)8 * NH * 32;
        #pragma unroll
        for (int kb = 0; kb < 4; kb++) {
            qh[kb][0] = g_qh[qA + kb*8 + tr];     qh[kb][1] = g_qh[qB + kb*8 + tr];
            qh[kb][2] = g_qh[qA + kb*8 + tr + 4]; qh[kb][3] = g_qh[qB + kb*8 + tr + 4];
        }
    }

    float o[8][4];
    #pragma unroll
    for (int ni = 0; ni < 8; ni++)
        #pragma unroll
        for (int j = 0; j < 4; j++) o[ni][j] = 0.f;
    float m0r = -1e30f, m1r = -1e30f, l0r = 0.f, l1r = 0.f;

    const size_t kbase = ((size_t)(b*T) * NKV + kv) * 32;
    const size_t vbase = ((size_t)(b*NKV + kv)) * (T/2) * 64;
    const uint32_t ONES = 0x3C003C00u;
    uint32_t bones[2] = {ONES, ONES};

    for (int kt = 0; kt <= qt; kt++) {
        const int t0 = kt * 64;
        __syncthreads();
        // K planes: verbatim 32-word rows (already permuted in global)
        #pragma unroll
        for (int ci = 0; ci < 4; ci++) {
            int i = tid + ci * 128;
            int r = i >> 3, j = (i & 7) * 4;
            size_t src = kbase + (size_t)(t0 + r) * (NKV*32) + j;
            *(uint4*)&Kh[r*KSTR + j] = *(const uint4*)&g_kh[src];
            *(uint4*)&Km[r*KSTR + j] = *(const uint4*)&g_km[src];
        }
        // V planes: verbatim 64-word t-pair rows (already permuted in global)
        #pragma unroll
        for (int ci = 0; ci < 4; ci++) {
            int i = tid + ci * 128;
            int tp = i >> 4, j = (i & 15) * 4;
            size_t src = vbase + (size_t)(t0/2 + tp) * 64 + j;
            *(uint4*)&Vh[tp*VSTR + j] = *(const uint4*)&g_vth[src];
            *(uint4*)&Vm[tp*VSTR + j] = *(const uint4*)&g_vtm[src];
        }
        __syncthreads();

        // ---- S = Q @ K^T: vector-LDS B fragments ----
        float s[8][4];
        #pragma unroll
        for (int ni = 0; ni < 8; ni++) {
            s[ni][0] = s[ni][1] = s[ni][2] = s[ni][3] = 0.f;
            const int kn = (ni*8 + tq) * KSTR;
            uint4 h0 = *(const uint4*)&Kh[kn + tr*4];        // u=tr,   kb 0..3
            uint4 h1 = *(const uint4*)&Kh[kn + tr*4 + 16];   // u=tr+4, kb 0..3
            uint4 mm0 = *(const uint4*)&Km[kn + tr*4];
            uint4 mm1 = *(const uint4*)&Km[kn + tr*4 + 16];
            uint32_t bh[2], bm[2];
            bh[0]=h0.x; bh[1]=h1.x; bm[0]=mm0.x; bm[1]=mm1.x;
            mma_f16(s[ni], qh[0], bh); mma_f16(s[ni], qh[0], bm);
            bh[0]=h0.y; bh[1]=h1.y; bm[0]=mm0.y; bm[1]=mm1.y;
            mma_f16(s[ni], qh[1], bh); mma_f16(s[ni], qh[1], bm);
            bh[0]=h0.z; bh[1]=h1.z; bm[0]=mm0.z; bm[1]=mm1.z;
            mma_f16(s[ni], qh[2], bh); mma_f16(s[ni], qh[2], bm);
            bh[0]=h0.w; bh[1]=h1.w; bm[0]=mm0.w; bm[1]=mm1.w;
            mma_f16(s[ni], qh[3], bh); mma_f16(s[ni], qh[3], bm);
        }

        // ---- causal mask (diagonal tile only) ----
        const int rowa = qt*64 + r0, rowb = rowa + 8;
        if (kt == qt) {
            #pragma unroll
            for (int ni = 0; ni < 8; ni++) {
                int col = t0 + ni*8 + 2*tr;
                if (col     > rowa) s[ni][0] = -1e30f;
                if (col + 1 > rowa) s[ni][1] = -1e30f;
                if (col     > rowb) s[ni][2] = -1e30f;
                if (col + 1 > rowb) s[ni][3] = -1e30f;
            }
        }

        // ---- online softmax: row max fp32, exps as fp16 pairs ----
        const float SC = 0.125f;
        float mx0 = -1e30f, mx1 = -1e30f;
        #pragma unroll
        for (int ni = 0; ni < 8; ni++) {
            mx0 = fmaxf(mx0, fmaxf(s[ni][0], s[ni][1]));
            mx1 = fmaxf(mx1, fmaxf(s[ni][2], s[ni][3]));
        }
        mx0 = fmaxf(mx0, __shfl_xor_sync(0xffffffffu, mx0, 1));
        mx0 = fmaxf(mx0, __shfl_xor_sync(0xffffffffu, mx0, 2));
        mx1 = fmaxf(mx1, __shfl_xor_sync(0xffffffffu, mx1, 1));
        mx1 = fmaxf(mx1, __shfl_xor_sync(0xffffffffu, mx1, 2));
        float mn0 = fmaxf(m0r, mx0 * SC);
        float mn1 = fmaxf(m1r, mx1 * SC);
        float al0 = exp2f((m0r - mn0) * LOG2E);
        float al1 = exp2f((m1r - mn1) * LOG2E);
        m0r = mn0; m1r = mn1;

        const float cf = SC * LOG2E;
        const float d0 = mn0 * LOG2E;
        const float d1 = mn1 * LOG2E;
        uint32_t pw[8][2];
        #pragma unroll
        for (int ni = 0; ni < 8; ni++) {
            pw[ni][0] = ex2_pair(fmaf(s[ni][0], cf, -d0), fmaf(s[ni][1], cf, -d0));
            pw[ni][1] = ex2_pair(fmaf(s[ni][2], cf, -d1), fmaf(s[ni][3], cf, -d1));
            o[ni][0] *= al0; o[ni][1] *= al0; o[ni][2] *= al1; o[ni][3] *= al1;
        }

        // ---- O += P @ V and l += P @ ones; vector-LDS V fragments ----
        float lacc[4] = {0.f, 0.f, 0.f, 0.f};
        #pragma unroll
        for (int c0 = 0; c0 < 4; c0++) {
            uint32_t ph[4] = {pw[2*c0][0], pw[2*c0][1], pw[2*c0+1][0], pw[2*c0+1][1]};
            mma_f16(lacc, ph, bones);
            const int ra = (c0*8 + tr) * VSTR + tq*8;
            const int rb = (c0*8 + tr + 4) * VSTR + tq*8;
            uint4 hA0 = *(const uint4*)&Vh[ra];        // ni 0..3, k-word0
            uint4 hA1 = *(const uint4*)&Vh[ra + 4];    // ni 4..7
            uint4 hB0 = *(const uint4*)&Vh[rb];
            uint4 hB1 = *(const uint4*)&Vh[rb + 4];
            uint4 mA0 = *(const uint4*)&Vm[ra];
            uint4 mA1 = *(const uint4*)&Vm[ra + 4];
            uint4 mB0 = *(const uint4*)&Vm[rb];
            uint4 mB1 = *(const uint4*)&Vm[rb + 4];
            uint32_t vh[2], vm[2];
            vh[0]=hA0.x; vh[1]=hB0.x; vm[0]=mA0.x; vm[1]=mB0.x;
            mma_f16(o[0], ph, vh); mma_f16(o[0], ph, vm);
            vh[0]=hA0.y; vh[1]=hB0.y; vm[0]=mA0.y; vm[1]=mB0.y;
            mma_f16(o[1], ph, vh); mma_f16(o[1], ph, vm);
            vh[0]=hA0.z; vh[1]=hB0.z; vm[0]=mA0.z; vm[1]=mB0.z;
            mma_f16(o[2], ph, vh); mma_f16(o[2], ph, vm);
            vh[0]=hA0.w; vh[1]=hB0.w; vm[0]=mA0.w; vm[1]=mB0.w;
            mma_f16(o[3], ph, vh); mma_f16(o[3], ph, vm);
            vh[0]=hA1.x; vh[1]=hB1.x; vm[0]=mA1.x; vm[1]=mB1.x;
            mma_f16(o[4], ph, vh); mma_f16(o[4], ph, vm);
            vh[0]=hA1.y; vh[1]=hB1.y; vm[0]=mA1.y; vm[1]=mB1.y;
            mma_f16(o[5], ph, vh); mma_f16(o[5], ph, vm);
            vh[0]=hA1.z; vh[1]=hB1.z; vm[0]=mA1.z; vm[1]=mB1.z;
            mma_f16(o[6], ph, vh); mma_f16(o[6], ph, vm);
            vh[0]=hA1.w; vh[1]=hB1.w; vm[0]=mA1.w; vm[1]=mB1.w;
            mma_f16(o[7], ph, vh); mma_f16(o[7], ph, vm);
        }
        l0r = l0r * al0 + lacc[0];
        l1r = l1r * al1 + lacc[2];
    }

    // ---- epilogue: y = o / l * gate ----
    const int rowa = qt*64 + r0, rowb = rowa + 8;
    float g0 = g_gate[(b*T + rowa) * NH + h] / l0r;
    float g1 = g_gate[(b*T + rowb) * NH + h] / l1r;
    #pragma unroll
    for (int ni = 0; ni < 8; ni++) {
        int col = ni*8 + 2*tr;
        size_t ba = ((size_t)(b*T + rowa) * NH + h) * HD + col;
        size_t bb = ((size_t)(b*T + rowb) * NH + h) * HD + col;
        *(float2*)(g_y + ba) = make_float2(o[ni][0] * g0, o[ni][1] * g0);
        *(float2*)(g_y + bb) = make_float2(o[ni][2] * g1, o[ni][3] * g1);
    }
}

// ---------------- launch ----------------
extern "C" void kernel_launch(void* const* d_in, const int* in_sizes, int n_in,
                              void* d_out, int out_size) {
    (void)in_sizes; (void)n_in; (void)out_size;
    const float* x  = (const float*)d_in[0];
    const float* qw = (const float*)d_in[1];
    const float* kw = (const float*)d_in[2];
    const float* vw = (const float*)d_in[3];
    const float* ow = (const float*)d_in[4];
    const float* ve = (const float*)d_in[5];
    const float* v0 = (const float*)d_in[6];
    const float* qg = (const float*)d_in[7];
    const float* vl = (const float*)d_in[8];
    const float* gw = (const float*)d_in[9];
    const float* gb = (const float*)d_in[10];

    float* out     = (float*)d_out;
    float* raw_out = out + (size_t)B * T * D;     // second output: raw_v

    // NTK-scaled base: T=2048 > TSL=1024
    const double nb = 10000.0 * pow((double)T / 1024.0, 64.0 / 62.0);

    // 1) fused QKV projections (+ V epilogue writes fp16 planes directly)
    gemm_bf16<<<dim3(12, (B*T)/128), 256>>>(x, qw, kw, vw, nullptr, ve, v0, vl,
                                            nullptr, raw_out, 0);

    // 2) merged rmsnorm+rope for Q and K -> packed fp16 planes
    rmsnorm_rope_pack<<<(B*T*(NH+NKV))/8, 256>>>(qg, nb);

    // 3) gate
    gate_kernel<<<B*T, 512>>>(x, gw, gb);

    // 4) fp16 tensor-core attention (4th launch -> ncu capture target)
    attn_f16<<<dim3(T/64, NH, B), 128>>>();

    // 5) output projection (bf16 3-pass)
    gemm_bf16<<<dim3(D/128, (B*T)/128), 256>>>(nullptr, nullptr, nullptr, nullptr, ow,
                                               nullptr, nullptr, nullptr, out, nullptr, 1);
}

// round 15
// speedup vs baseline: 1.9633x; 1.9633x over previous
#include <cuda_runtime.h>
#include <cuda_fp16.h>
#include <math.h>
#include <stdint.h>

#define B   2
#define T   2048
#define D   1024
#define NH  16
#define NKV 4
#define HD  64
#define GQ  4            // NH / NKV
#define EPSF 1.1920929e-07f
#define LOG2E 1.4426950408889634f
#define PSTR 12          // GEMM smem word stride (8 data + 4 pad) -> conflict-free frags
#define KSTR 48          // attn K plane stride: conflict-free LDS.128
#define VSTR 68          // attn V plane stride: near-conflict-free LDS.128
#define XWORDS (B*T*(D/2))       // 2097152 words (x / y planes)
#define WROWS  (NH*HD + NKV*HD + NKV*HD + D)   // 2560 weight rows
#define WWORDS (WROWS*(D/2))     // 1310720 words

// ---------------- scratch (no allocations allowed) ----------------
__device__ float    g_q[B*T*NH*HD];        // q projection (fp32)
__device__ float    g_k[B*T*NKV*HD];       // k projection (fp32)
__device__ float    g_v[B*T*NKV*HD];       // v mixed (fp32)
__device__ float    g_y[B*T*NH*HD];        // attention output (gate folded in)
__device__ float    g_gate[B*T*NH];        // sigmoid gate
__device__ uint32_t g_qh[B*T*NH*(HD/2)];   // q normed/roped/gained fp16x2 (unpermuted)
__device__ uint32_t g_kh[B*T*NKV*(HD/2)];  // k hi plane  (permuted word layout)
__device__ uint32_t g_km[B*T*NKV*(HD/2)];  // k mid plane
__device__ uint32_t g_vth[B*NKV*(T/2)*HD]; // v hi plane [b][kv][t/2][pd]
__device__ uint32_t g_vtm[B*NKV*(T/2)*HD]; // v mid plane
// pre-split GEMM operand planes (bf16x2 hi/mid)
__device__ uint32_t g_xh[XWORDS], g_xm[XWORDS];   // x
__device__ uint32_t g_wh[WWORDS], g_wm[WWORDS];   // [qw;kw;vw;ow] rows
__device__ uint32_t g_yh[XWORDS], g_ym[XWORDS];   // y (attention output)
// rope trig tables (fp32, computed once in double)
__device__ float    g_ct[T*32], g_st[T*32];

// ---------------- mma helpers ----------------
__device__ __forceinline__ void mma_bf16(float* c, const uint32_t* a, const uint32_t* b) {
    asm volatile(
        "mma.sync.aligned.m16n8k16.row.col.f32.bf16.bf16.f32 "
        "{%0,%1,%2,%3}, {%4,%5,%6,%7}, {%8,%9}, {%0,%1,%2,%3};\n"
        : "+f"(c[0]), "+f"(c[1]), "+f"(c[2]), "+f"(c[3])
        : "r"(a[0]), "r"(a[1]), "r"(a[2]), "r"(a[3]), "r"(b[0]), "r"(b[1]));
}
__device__ __forceinline__ void mma_f16(float* c, const uint32_t* a, const uint32_t* b) {
    asm volatile(
        "mma.sync.aligned.m16n8k16.row.col.f32.f16.f16.f32 "
        "{%0,%1,%2,%3}, {%4,%5,%6,%7}, {%8,%9}, {%0,%1,%2,%3};\n"
        : "+f"(c[0]), "+f"(c[1]), "+f"(c[2]), "+f"(c[3])
        : "r"(a[0]), "r"(a[1]), "r"(a[2]), "r"(a[3]), "r"(b[0]), "r"(b[1]));
}

// bf16 split: (x0,x1) -> hi word + residual word
__device__ __forceinline__ void split2_pack(float x0, float x1, uint32_t& wh, uint32_t& wm) {
    asm("cvt.rn.bf16x2.f32 %0, %1, %2;" : "=r"(wh) : "f"(x1), "f"(x0));
    float h0 = __uint_as_float(wh << 16);
    float h1 = __uint_as_float(wh & 0xffff0000u);
    asm("cvt.rn.bf16x2.f32 %0, %1, %2;" : "=r"(wm) : "f"(x1 - h1), "f"(x0 - h0));
}
// fp16 split
__device__ __forceinline__ void split2_pack_f16(float x0, float x1, uint32_t& wh, uint32_t& wm) {
    __half2 h = __floats2half2_rn(x0, x1);
    wh = *(uint32_t*)&h;
    float2 hf = __half22float2(h);
    __half2 m = __floats2half2_rn(x0 - hf.x, x1 - hf.y);
    wm = *(uint32_t*)&m;
}
// 2 exponentials in one MUFU op
__device__ __forceinline__ uint32_t ex2_pair(float a0, float a1) {
    uint32_t w, r;
    asm("cvt.rn.satfinite.f16x2.f32 %0, %1, %2;" : "=r"(w) : "f"(a1), "f"(a0));
    asm("ex2.approx.f16x2 %0, %1;" : "=r"(r) : "r"(w));
    return r;
}

// ---------------- pre-split kernels ----------------
__global__ void split_in(const float* __restrict__ x, const float* __restrict__ qw,
                         const float* __restrict__ kw, const float* __restrict__ vw,
                         const float* __restrict__ ow) {
    int idx = blockIdx.x * 256 + threadIdx.x;
    uint32_t h, m;
    if (idx < XWORDS) {
        float2 v = *(const float2*)(x + 2 * (size_t)idx);
        split2_pack(v.x, v.y, h, m);
        g_xh[idx] = h; g_xm[idx] = m;
    } else {
        int wi = idx - XWORDS;
        if (wi >= WWORDS) return;
        int row = wi >> 9, col = wi & 511;
        const float* src; int r;
        if (row < 1024)      { src = qw; r = row; }
        else if (row < 1280) { src = kw; r = row - 1024; }
        else if (row < 1536) { src = vw; r = row - 1280; }
        else                 { src = ow; r = row - 1536; }
        float2 v = *(const float2*)(src + (size_t)r * D + 2 * col);
        split2_pack(v.x, v.y, h, m);
        g_wh[wi] = h; g_wm[wi] = m;
    }
}
__global__ void split_y() {
    int idx = blockIdx.x * 256 + threadIdx.x;
    float2 v = *(const float2*)(g_y + 2 * (size_t)idx);
    uint32_t h, m;
    split2_pack(v.x, v.y, h, m);
    g_yh[idx] = h; g_ym[idx] = m;
}

// ---------------- trig table: fp64 hoisted to 65K unique (t, freq) pairs ----------------
__global__ void trig_table(double nb) {
    int idx = blockIdx.x * 256 + threadIdx.x;   // T*32
    int t = idx >> 5, lane = idx & 31;
    float inv = (float)pow(nb, -(double)(2 * lane) / (double)HD);
    float fr  = (float)t * inv;
    g_ct[idx] = (float)cos((double)fr);
    g_st[idx] = (float)sin((double)fr);
}

// ---------------- GEMM on pre-split planes: zero in-loop split ALU ----------------
// job=0: QKV fused. grid.x: [0,8)=Q, [8,10)=K, [10,12)=V (+v fp32 epilogue).
// job=1: O projection (A = y planes, C = out).
__global__ __launch_bounds__(256)
void gemm_bf16(const float* __restrict__ ve, const float* __restrict__ v0,
               const float* __restrict__ lam,
               float* __restrict__ out, float* __restrict__ raw_out, int job) {
    __shared__ uint32_t Ah[2][128*PSTR], Am[2][128*PSTR];
    __shared__ uint32_t Bh[2][128*PSTR], Bm[2][128*PSTR];

    const uint32_t *ap, *amp;
    float* C = nullptr; int N, n0, wr0; bool vjob = false;
    if (job == 0) {
        ap = g_xh; amp = g_xm;
        int bx = blockIdx.x;
        if (bx < 8)       { C = g_q; N = NH*HD;  n0 = bx * 128; wr0 = 0; }
        else if (bx < 10) { C = g_k; N = NKV*HD; n0 = (bx - 8) * 128; wr0 = 1024; }
        else              { C = g_v; N = NKV*HD; n0 = (bx - 10) * 128; wr0 = 1280; vjob = true; }
    } else {
        ap = g_yh; amp = g_ym; C = out; N = D; n0 = blockIdx.x * 128; wr0 = 1536;
    }
    const int m0 = blockIdx.y * 128;

    const int tid  = threadIdx.x;
    const int lane = tid & 31;
    const int w    = tid >> 5;
    const int wm   = w & 1;
    const int wn   = w >> 1;
    const int tq   = lane >> 2;
    const int tr   = lane & 3;

    const int lrow = tid >> 1;           // 0..127
    const int lw   = (tid & 1) * 4;      // word col 0 or 4

    const size_t aoff = (size_t)(m0 + lrow) * 512 + lw;
    const size_t boff = (size_t)(wr0 + n0 + lrow) * 512 + lw;
    const int so = lrow * PSTR + lw;

    float c[16][4];
    #pragma unroll
    for (int i = 0; i < 16; i++)
        #pragma unroll
        for (int j = 0; j < 4; j++) c[i][j] = 0.f;

    *(uint4*)&Ah[0][so] = *(const uint4*)&ap[aoff];
    *(uint4*)&Am[0][so] = *(const uint4*)&amp[aoff];
    *(uint4*)&Bh[0][so] = *(const uint4*)&g_wh[boff];
    *(uint4*)&Bm[0][so] = *(const uint4*)&g_wm[boff];
    __syncthreads();

    const int niter = D / 16;   // 8 words per iter
    int cur = 0;
    for (int it = 0; it < niter; it++) {
        uint4 pah, pam, pbh, pbm;
        const bool has_next = (it + 1 < niter);
        if (has_next) {
            int kw = (it + 1) * 8;
            pah = *(const uint4*)&ap[aoff + kw];
            pam = *(const uint4*)&amp[aoff + kw];
            pbh = *(const uint4*)&g_wh[boff + kw];
            pbm = *(const uint4*)&g_wm[boff + kw];
        }

        const uint32_t* ah = Ah[cur]; const uint32_t* am = Am[cur];
        const uint32_t* bh = Bh[cur]; const uint32_t* bm = Bm[cur];

        uint32_t afh[4][4], afm[4][4], bfh[4][2], bfm[4][2];
        #pragma unroll
        for (int mi = 0; mi < 4; mi++) {
            int r = wm * 64 + mi * 16 + tq;
            afh[mi][0] = ah[r*PSTR + tr];     afh[mi][1] = ah[(r+8)*PSTR + tr];
            afh[mi][2] = ah[r*PSTR + tr + 4]; afh[mi][3] = ah[(r+8)*PSTR + tr + 4];
            afm[mi][0] = am[r*PSTR + tr];     afm[mi][1] = am[(r+8)*PSTR + tr];
            afm[mi][2] = am[r*PSTR + tr + 4]; afm[mi][3] = am[(r+8)*PSTR + tr + 4];
        }
        #pragma unroll
        for (int ni = 0; ni < 4; ni++) {
            int rn = wn * 32 + ni * 8 + tq;
            bfh[ni][0] = bh[rn*PSTR + tr]; bfh[ni][1] = bh[rn*PSTR + tr + 4];
            bfm[ni][0] = bm[rn*PSTR + tr]; bfm[ni][1] = bm[rn*PSTR + tr + 4];
        }
        #pragma unroll
        for (int mi = 0; mi < 4; mi++)
            #pragma unroll
            for (int ni = 0; ni < 4; ni++) {
                mma_bf16(c[mi*4+ni], afh[mi], bfh[ni]);
                mma_bf16(c[mi*4+ni], afh[mi], bfm[ni]);
                mma_bf16(c[mi*4+ni], afm[mi], bfh[ni]);
            }

        if (has_next) {
            int nxt = cur ^ 1;
            *(uint4*)&Ah[nxt][so] = pah;
            *(uint4*)&Am[nxt][so] = pam;
            *(uint4*)&Bh[nxt][so] = pbh;
            *(uint4*)&Bm[nxt][so] = pbm;
            __syncthreads();
            cur = nxt;
        }
    }

    if (!vjob) {
        #pragma unroll
        for (int mi = 0; mi < 4; mi++)
            #pragma unroll
            for (int ni = 0; ni < 4; ni++) {
                int row = m0 + wm*64 + mi*16 + tq;
                int col = n0 + wn*32 + ni*8 + 2*tr;
                float* cp = c[mi*4+ni];
                *(float2*)(C + (size_t)row * N + col)       = make_float2(cp[0], cp[1]);
                *(float2*)(C + (size_t)(row + 8) * N + col) = make_float2(cp[2], cp[3]);
            }
    } else {
        const float l0 = lam[0], l1 = lam[1];
        #pragma unroll
        for (int mi = 0; mi < 4; mi++)
            #pragma unroll
            for (int ni = 0; ni < 4; ni++) {
                int row = m0 + wm*64 + mi*16 + tq;
                int col = n0 + wn*32 + ni*8 + 2*tr;
                float* cp = c[mi*4+ni];
                #pragma unroll
                for (int half = 0; half < 2; half++) {
                    size_t gi = (size_t)(row + half*8) * N + col;
                    float2 vee = *(const float2*)(ve + gi);
                    float2 v00 = *(const float2*)(v0 + gi);
                    float r0 = cp[half*2]   + vee.x;
                    float r1 = cp[half*2+1] + vee.y;
                    *(float2*)(raw_out + gi) = make_float2(r0, r1);
                    *(float2*)(g_v + gi) = make_float2(l0*v00.x + l1*r0, l0*v00.y + l1*r1);
                }
            }
    }
}

// ---------------- merged RMSNorm + RoPE (+gain), trig from table ----------------
__global__ void rmsnorm_rope_pack(const float* __restrict__ gain) {
    int grow = blockIdx.x * 8 + (threadIdx.x >> 5);
    int lane = threadIdx.x & 31;
    const bool isQ = grow < B*T*NH;
    int row = isQ ? grow : grow - B*T*NH;
    int H   = isQ ? NH : NKV;
    const float* src = isQ ? g_q : g_k;
    int t = (row / H) % T;
    int h = row % H;
    const float* p = src + (size_t)row * HD;

    float a  = p[lane];
    float b2 = p[lane + 32];
    float ss = a*a + b2*b2;
    #pragma unroll
    for (int o = 16; o; o >>= 1) ss += __shfl_xor_sync(0xffffffffu, ss, o);
    float r = rsqrtf(ss * (1.0f/HD) + EPSF);
    a *= r; b2 *= r;

    float cc = g_ct[t * 32 + lane];
    float sn = g_st[t * 32 + lane];

    float o1 =  a*cc + b2*sn;          // d = lane
    float o2 = -a*sn + b2*cc;          // d = lane + 32
    if (isQ) { float gg = gain[h]; o1 *= gg; o2 *= gg; }

    float p1 = __shfl_xor_sync(0xffffffffu, o1, 1);
    float p2 = __shfl_xor_sync(0xffffffffu, o2, 1);
    uint32_t wh, wmv; int widx;
    if (lane & 1) { split2_pack_f16(p2, o2, wh, wmv); widx = 16 + (lane >> 1); }
    else          { split2_pack_f16(o1, p1, wh, wmv); widx = lane >> 1; }
    if (isQ) {
        g_qh[(size_t)row * 32 + widx] = wh;
    } else {
        int pidx = (widx & 7)*4 + (widx >> 3);   // permute for LDS.128 fragments
        g_kh[(size_t)row * 32 + pidx] = wh;
        g_km[(size_t)row * 32 + pidx] = wmv;
    }
}

// ---------------- V pack: g_v -> t-pair permuted fp16 planes ----------------
__global__ void v_pack() {
    int idx = blockIdx.x * 256 + threadIdx.x;
    int d  = idx & 63;
    int tp = (idx >> 6) & (T/2 - 1);
    int kv = (idx >> 16) & 3;
    int b  = idx >> 18;
    float a  = g_v[((size_t)(b*T + 2*tp)     * NKV + kv) * HD + d];
    float b2 = g_v[((size_t)(b*T + 2*tp + 1) * NKV + kv) * HD + d];
    uint32_t wh, wmv;
    split2_pack_f16(a, b2, wh, wmv);
    size_t vb = ((size_t)(b*NKV + kv) * (T/2) + tp) * 64;
    int pd = (d & 7)*8 + (d >> 3);
    g_vth[vb + pd] = wh;
    g_vtm[vb + pd] = wmv;
}

// ---------------- gate: sigmoid(x @ gate_w^T + gate_b) ----------------
__global__ void gate_kernel(const float* __restrict__ x, const float* __restrict__ gw,
                            const float* __restrict__ gb) {
    __shared__ float xs[D];
    int bt = blockIdx.x;
    for (int i = threadIdx.x; i < D; i += 512) xs[i] = x[(size_t)bt * D + i];
    __syncthreads();
    int h = threadIdx.x >> 5, lane = threadIdx.x & 31;
    const float* w = gw + (size_t)h * D;
    float s = 0.f;
    for (int i = lane; i < D; i += 32) s += xs[i] * w[i];
    #pragma unroll
    for (int o = 16; o; o >>= 1) s += __shfl_xor_sync(0xffffffffu, s, o);
    if (lane == 0) g_gate[bt * NH + h] = 1.0f / (1.0f + __expf(-(s + gb[h])));
}

// ---------------- fp16 flash attention (R14 proven: vector-LDS fragments) ----------------
__global__ __launch_bounds__(128)
void attn_f16() {
    __shared__ uint32_t Kh[64*KSTR], Km[64*KSTR];   // [key n][permuted word]
    __shared__ uint32_t Vh[32*VSTR], Vm[32*VSTR];   // [t-pair][permuted d]

    const int qt = (int)gridDim.x - 1 - (int)blockIdx.x;
    const int h = blockIdx.y, b = blockIdx.z;
    const int kv = h / GQ;
    const int tid = threadIdx.x;
    const int w = tid >> 5, lane = tid & 31;
    const int tq = lane >> 2, tr = lane & 3;
    const int r0 = w * 16 + tq;

    uint32_t qh[4][4];
    {
        const size_t qA = ((size_t)(b*T + qt*64 + r0) * NH + h) * 32;
        const size_t qB = qA + (size_t)8 * NH * 32;
        #pragma unroll
        for (int kb = 0; kb < 4; kb++) {
            qh[kb][0] = g_qh[qA + kb*8 + tr];     qh[kb][1] = g_qh[qB + kb*8 + tr];
            qh[kb][2] = g_qh[qA + kb*8 + tr + 4]; qh[kb][3] = g_qh[qB + kb*8 + tr + 4];
        }
    }

    float o[8][4];
    #pragma unroll
    for (int ni = 0; ni < 8; ni++)
        #pragma unroll
        for (int j = 0; j < 4; j++) o[ni][j] = 0.f;
    float m0r = -1e30f, m1r = -1e30f, l0r = 0.f, l1r = 0.f;

    const size_t kbase = ((size_t)(b*T) * NKV + kv) * 32;
    const size_t vbase = ((size_t)(b*NKV + kv)) * (T/2) * 64;
    const uint32_t ONES = 0x3C003C00u;
    uint32_t bones[2] = {ONES, ONES};

    for (int kt = 0; kt <= qt; kt++) {
        const int t0 = kt * 64;
        __syncthreads();
        #pragma unroll
        for (int ci = 0; ci < 4; ci++) {
            int i = tid + ci * 128;
            int r = i >> 3, j = (i & 7) * 4;
            size_t src = kbase + (size_t)(t0 + r) * (NKV*32) + j;
            *(uint4*)&Kh[r*KSTR + j] = *(const uint4*)&g_kh[src];
            *(uint4*)&Km[r*KSTR + j] = *(const uint4*)&g_km[src];
        }
        #pragma unroll
        for (int ci = 0; ci < 4; ci++) {
            int i = tid + ci * 128;
            int tp = i >> 4, j = (i & 15) * 4;
            size_t src = vbase + (size_t)(t0/2 + tp) * 64 + j;
            *(uint4*)&Vh[tp*VSTR + j] = *(const uint4*)&g_vth[src];
            *(uint4*)&Vm[tp*VSTR + j] = *(const uint4*)&g_vtm[src];
        }
        __syncthreads();

        float s[8][4];
        #pragma unroll
        for (int ni = 0; ni < 8; ni++) {
            s[ni][0] = s[ni][1] = s[ni][2] = s[ni][3] = 0.f;
            const int kn = (ni*8 + tq) * KSTR;
            uint4 h0 = *(const uint4*)&Kh[kn + tr*4];
            uint4 h1 = *(const uint4*)&Kh[kn + tr*4 + 16];
            uint4 mm0 = *(const uint4*)&Km[kn + tr*4];
            uint4 mm1 = *(const uint4*)&Km[kn + tr*4 + 16];
            uint32_t bh[2], bm[2];
            bh[0]=h0.x; bh[1]=h1.x; bm[0]=mm0.x; bm[1]=mm1.x;
            mma_f16(s[ni], qh[0], bh); mma_f16(s[ni], qh[0], bm);
            bh[0]=h0.y; bh[1]=h1.y; bm[0]=mm0.y; bm[1]=mm1.y;
            mma_f16(s[ni], qh[1], bh); mma_f16(s[ni], qh[1], bm);
            bh[0]=h0.z; bh[1]=h1.z; bm[0]=mm0.z; bm[1]=mm1.z;
            mma_f16(s[ni], qh[2], bh); mma_f16(s[ni], qh[2], bm);
            bh[0]=h0.w; bh[1]=h1.w; bm[0]=mm0.w; bm[1]=mm1.w;
            mma_f16(s[ni], qh[3], bh); mma_f16(s[ni], qh[3], bm);
        }

        const int rowa = qt*64 + r0, rowb = rowa + 8;
        if (kt == qt) {
            #pragma unroll
            for (int ni = 0; ni < 8; ni++) {
                int col = t0 + ni*8 + 2*tr;
                if (col     > rowa) s[ni][0] = -1e30f;
                if (col + 1 > rowa) s[ni][1] = -1e30f;
                if (col     > rowb) s[ni][2] = -1e30f;
                if (col + 1 > rowb) s[ni][3] = -1e30f;
            }
        }

        const float SC = 0.125f;
        float mx0 = -1e30f, mx1 = -1e30f;
        #pragma unroll
        for (int ni = 0; ni < 8; ni++) {
            mx0 = fmaxf(mx0, fmaxf(s[ni][0], s[ni][1]));
            mx1 = fmaxf(mx1, fmaxf(s[ni][2], s[ni][3]));
        }
        mx0 = fmaxf(mx0, __shfl_xor_sync(0xffffffffu, mx0, 1));
        mx0 = fmaxf(mx0, __shfl_xor_sync(0xffffffffu, mx0, 2));
        mx1 = fmaxf(mx1, __shfl_xor_sync(0xffffffffu, mx1, 1));
        mx1 = fmaxf(mx1, __shfl_xor_sync(0xffffffffu, mx1, 2));
        float mn0 = fmaxf(m0r, mx0 * SC);
        float mn1 = fmaxf(m1r, mx1 * SC);
        float al0 = exp2f((m0r - mn0) * LOG2E);
        float al1 = exp2f((m1r - mn1) * LOG2E);
        m0r = mn0; m1r = mn1;

        const float cf = SC * LOG2E;
        const float d0 = mn0 * LOG2E;
        const float d1 = mn1 * LOG2E;
        uint32_t pw[8][2];
        #pragma unroll
        for (int ni = 0; ni < 8; ni++) {
            pw[ni][0] = ex2_pair(fmaf(s[ni][0], cf, -d0), fmaf(s[ni][1], cf, -d0));
            pw[ni][1] = ex2_pair(fmaf(s[ni][2], cf, -d1), fmaf(s[ni][3], cf, -d1));
            o[ni][0] *= al0; o[ni][1] *= al0; o[ni][2] *= al1; o[ni][3] *= al1;
        }

        float lacc[4] = {0.f, 0.f, 0.f, 0.f};
        #pragma unroll
        for (int c0 = 0; c0 < 4; c0++) {
            uint32_t ph[4] = {pw[2*c0][0], pw[2*c0][1], pw[2*c0+1][0], pw[2*c0+1][1]};
            mma_f16(lacc, ph, bones);
            const int ra = (c0*8 + tr) * VSTR + tq*8;
            const int rb = (c0*8 + tr + 4) * VSTR + tq*8;
            uint4 hA0 = *(const uint4*)&Vh[ra];
            uint4 hA1 = *(const uint4*)&Vh[ra + 4];
            uint4 hB0 = *(const uint4*)&Vh[rb];
            uint4 hB1 = *(const uint4*)&Vh[rb + 4];
            uint4 mA0 = *(const uint4*)&Vm[ra];
            uint4 mA1 = *(const uint4*)&Vm[ra + 4];
            uint4 mB0 = *(const uint4*)&Vm[rb];
            uint4 mB1 = *(const uint4*)&Vm[rb + 4];
            uint32_t vh[2], vm[2];
            vh[0]=hA0.x; vh[1]=hB0.x; vm[0]=mA0.x; vm[1]=mB0.x;
            mma_f16(o[0], ph, vh); mma_f16(o[0], ph, vm);
            vh[0]=hA0.y; vh[1]=hB0.y; vm[0]=mA0.y; vm[1]=mB0.y;
            mma_f16(o[1], ph, vh); mma_f16(o[1], ph, vm);
            vh[0]=hA0.z; vh[1]=hB0.z; vm[0]=mA0.z; vm[1]=mB0.z;
            mma_f16(o[2], ph, vh); mma_f16(o[2], ph, vm);
            vh[0]=hA0.w; vh[1]=hB0.w; vm[0]=mA0.w; vm[1]=mB0.w;
            mma_f16(o[3], ph, vh); mma_f16(o[3], ph, vm);
            vh[0]=hA1.x; vh[1]=hB1.x; vm[0]=mA1.x; vm[1]=mB1.x;
            mma_f16(o[4], ph, vh); mma_f16(o[4], ph, vm);
            vh[0]=hA1.y; vh[1]=hB1.y; vm[0]=mA1.y; vm[1]=mB1.y;
            mma_f16(o[5], ph, vh); mma_f16(o[5], ph, vm);
            vh[0]=hA1.z; vh[1]=hB1.z; vm[0]=mA1.z; vm[1]=mB1.z;
            mma_f16(o[6], ph, vh); mma_f16(o[6], ph, vm);
            vh[0]=hA1.w; vh[1]=hB1.w; vm[0]=mA1.w; vm[1]=mB1.w;
            mma_f16(o[7], ph, vh); mma_f16(o[7], ph, vm);
        }
        l0r = l0r * al0 + lacc[0];
        l1r = l1r * al1 + lacc[2];
    }

    const int rowa = qt*64 + r0, rowb = rowa + 8;
    float g0 = g_gate[(b*T + rowa) * NH + h] / l0r;
    float g1 = g_gate[(b*T + rowb) * NH + h] / l1r;
    #pragma unroll
    for (int ni = 0; ni < 8; ni++) {
        int col = ni*8 + 2*tr;
        size_t ba = ((size_t)(b*T + rowa) * NH + h) * HD + col;
        size_t bb = ((size_t)(b*T + rowb) * NH + h) * HD + col;
        *(float2*)(g_y + ba) = make_float2(o[ni][0] * g0, o[ni][1] * g0);
        *(float2*)(g_y + bb) = make_float2(o[ni][2] * g1, o[ni][3] * g1);
    }
}

// ---------------- launch ----------------
extern "C" void kernel_launch(void* const* d_in, const int* in_sizes, int n_in,
                              void* d_out, int out_size) {
    (void)in_sizes; (void)n_in; (void)out_size;
    const float* x  = (const float*)d_in[0];
    const float* qw = (const float*)d_in[1];
    const float* kw = (const float*)d_in[2];
    const float* vw = (const float*)d_in[3];
    const float* ow = (const float*)d_in[4];
    const float* ve = (const float*)d_in[5];
    const float* v0 = (const float*)d_in[6];
    const float* qg = (const float*)d_in[7];
    const float* vl = (const float*)d_in[8];
    const float* gw = (const float*)d_in[9];
    const float* gb = (const float*)d_in[10];

    float* out     = (float*)d_out;
    float* raw_out = out + (size_t)B * T * D;     // second output: raw_v

    // NTK-scaled base: T=2048 > TSL=1024
    const double nb = 10000.0 * pow((double)T / 1024.0, 64.0 / 62.0);

    // 1) pre-split x + all weights into bf16 hi/mid planes
    split_in<<<(XWORDS + WWORDS + 255) / 256, 256>>>(x, qw, kw, vw, ow);

    // 2) rope trig table (fp64 hoisted to 65K threads)
    trig_table<<<(T*32)/256, 256>>>(nb);

    // 3) fused QKV projections (+ V fp32 epilogue)
    gemm_bf16<<<dim3(12, (B*T)/128), 256>>>(ve, v0, vl, nullptr, raw_out, 0);

    // 4) merged rmsnorm+rope -> packed fp16 planes (table trig)
    rmsnorm_rope_pack<<<(B*T*(NH+NKV))/8, 256>>>(qg);

    // 5) pack mixed V into permuted t-pair fp16 planes
    v_pack<<<(B*NKV*(T/2)*HD)/256, 256>>>();

    // 6) gate
    gate_kernel<<<B*T, 512>>>(x, gw, gb);

    // 7) fp16 tensor-core attention
    attn_f16<<<dim3(T/64, NH, B), 128>>>();

    // 8) split attention output for O projection
    split_y<<<XWORDS/256, 256>>>();

    // 9) output projection
    gemm_bf16<<<dim3(D/128, (B*T)/128), 256>>>(nullptr, nullptr, nullptr, out, nullptr, 1);
}

// round 17
// speedup vs baseline: 1.9832x; 1.0101x over previous
#include <cuda_runtime.h>
#include <cuda_fp16.h>
#include <math.h>
#include <stdint.h>

#define B   2
#define T   2048
#define D   1024
#define NH  16
#define NKV 4
#define HD  64
#define GQ  4            // NH / NKV
#define EPSF 1.1920929e-07f
#define LOG2E 1.4426950408889634f
#define PSTR 12          // GEMM smem word stride
#define KSTR 48          // attn K plane stride: conflict-free LDS.128
#define VSTR 68          // attn V plane stride: near-conflict-free LDS.128
#define XWORDS (B*T*(D/2))
#define WROWS  (NH*HD + NKV*HD + NKV*HD + D)
#define WWORDS (WROWS*(D/2))

// ---------------- scratch ----------------
__device__ float    g_q[B*T*NH*HD];
__device__ float    g_k[B*T*NKV*HD];
__device__ float    g_v[B*T*NKV*HD];
__device__ float    g_y[B*T*NH*HD];
__device__ float    g_gate[B*T*NH];
__device__ uint32_t g_qh[B*T*NH*(HD/2)];
__device__ uint32_t g_kh[B*T*NKV*(HD/2)];
__device__ uint32_t g_km[B*T*NKV*(HD/2)];
__device__ uint32_t g_vth[B*NKV*(T/2)*HD];
__device__ uint32_t g_vtm[B*NKV*(T/2)*HD];
__device__ uint32_t g_xh[XWORDS], g_xm[XWORDS];
__device__ uint32_t g_wh[WWORDS], g_wm[WWORDS];
__device__ uint32_t g_yh[XWORDS], g_ym[XWORDS];
__device__ float    g_ct[T*32], g_st[T*32];

// ---------------- mma helpers ----------------
__device__ __forceinline__ void mma_bf16(float* c, const uint32_t* a, const uint32_t* b) {
    asm volatile(
        "mma.sync.aligned.m16n8k16.row.col.f32.bf16.bf16.f32 "
        "{%0,%1,%2,%3}, {%4,%5,%6,%7}, {%8,%9}, {%0,%1,%2,%3};\n"
        : "+f"(c[0]), "+f"(c[1]), "+f"(c[2]), "+f"(c[3])
        : "r"(a[0]), "r"(a[1]), "r"(a[2]), "r"(a[3]), "r"(b[0]), "r"(b[1]));
}
__device__ __forceinline__ void mma_f16(float* c, const uint32_t* a, const uint32_t* b) {
    asm volatile(
        "mma.sync.aligned.m16n8k16.row.col.f32.f16.f16.f32 "
        "{%0,%1,%2,%3}, {%4,%5,%6,%7}, {%8,%9}, {%0,%1,%2,%3};\n"
        : "+f"(c[0]), "+f"(c[1]), "+f"(c[2]), "+f"(c[3])
        : "r"(a[0]), "r"(a[1]), "r"(a[2]), "r"(a[3]), "r"(b[0]), "r"(b[1]));
}

__device__ __forceinline__ void split2_pack(float x0, float x1, uint32_t& wh, uint32_t& wm) {
    asm("cvt.rn.bf16x2.f32 %0, %1, %2;" : "=r"(wh) : "f"(x1), "f"(x0));
    float h0 = __uint_as_float(wh << 16);
    float h1 = __uint_as_float(wh & 0xffff0000u);
    asm("cvt.rn.bf16x2.f32 %0, %1, %2;" : "=r"(wm) : "f"(x1 - h1), "f"(x0 - h0));
}
__device__ __forceinline__ void split2_pack_f16(float x0, float x1, uint32_t& wh, uint32_t& wm) {
    __half2 h = __floats2half2_rn(x0, x1);
    wh = *(uint32_t*)&h;
    float2 hf = __half22float2(h);
    __half2 m = __floats2half2_rn(x0 - hf.x, x1 - hf.y);
    wm = *(uint32_t*)&m;
}
__device__ __forceinline__ uint32_t ex2_pair(float a0, float a1) {
    uint32_t w, r;
    asm("cvt.rn.satfinite.f16x2.f32 %0, %1, %2;" : "=r"(w) : "f"(a1), "f"(a0));
    asm("ex2.approx.f16x2 %0, %1;" : "=r"(r) : "r"(w));
    return r;
}

// ---------------- pre-split kernels ----------------
__global__ void split_in(const float* __restrict__ x, const float* __restrict__ qw,
                         const float* __restrict__ kw, const float* __restrict__ vw,
                         const float* __restrict__ ow) {
    int idx = blockIdx.x * 256 + threadIdx.x;
    uint32_t h, m;
    if (idx < XWORDS) {
        float2 v = *(const float2*)(x + 2 * (size_t)idx);
        split2_pack(v.x, v.y, h, m);
        g_xh[idx] = h; g_xm[idx] = m;
    } else {
        int wi = idx - XWORDS;
        if (wi >= WWORDS) return;
        int row = wi >> 9, col = wi & 511;
        const float* src; int r;
        if (row < 1024)      { src = qw; r = row; }
        else if (row < 1280) { src = kw; r = row - 1024; }
        else if (row < 1536) { src = vw; r = row - 1280; }
        else                 { src = ow; r = row - 1536; }
        float2 v = *(const float2*)(src + (size_t)r * D + 2 * col);
        split2_pack(v.x, v.y, h, m);
        g_wh[wi] = h; g_wm[wi] = m;
    }
}
__global__ void split_y() {
    int idx = blockIdx.x * 256 + threadIdx.x;
    float2 v = *(const float2*)(g_y + 2 * (size_t)idx);
    uint32_t h, m;
    split2_pack(v.x, v.y, h, m);
    g_yh[idx] = h; g_ym[idx] = m;
}

// ---------------- trig table (fp64 hoisted) ----------------
__global__ void trig_table(double nb) {
    int idx = blockIdx.x * 256 + threadIdx.x;
    int t = idx >> 5, lane = idx & 31;
    float inv = (float)pow(nb, -(double)(2 * lane) / (double)HD);
    float fr  = (float)t * inv;
    g_ct[idx] = (float)cos((double)fr);
    g_st[idx] = (float)sin((double)fr);
}

// ---------------- GEMM on pre-split planes, pass-outer MMA ordering (16-way ILP) ----------------
__global__ __launch_bounds__(256)
void gemm_bf16(const float* __restrict__ ve, const float* __restrict__ v0,
               const float* __restrict__ lam,
               float* __restrict__ out, float* __restrict__ raw_out, int job) {
    __shared__ uint32_t Ah[2][128*PSTR], Am[2][128*PSTR];
    __shared__ uint32_t Bh[2][128*PSTR], Bm[2][128*PSTR];

    const uint32_t *ap, *amp;
    float* C = nullptr; int N, n0, wr0; bool vjob = false;
    if (job == 0) {
        ap = g_xh; amp = g_xm;
        int bx = blockIdx.x;
        if (bx < 8)       { C = g_q; N = NH*HD;  n0 = bx * 128; wr0 = 0; }
        else if (bx < 10) { C = g_k; N = NKV*HD; n0 = (bx - 8) * 128; wr0 = 1024; }
        else              { C = g_v; N = NKV*HD; n0 = (bx - 10) * 128; wr0 = 1280; vjob = true; }
    } else {
        ap = g_yh; amp = g_ym; C = out; N = D; n0 = blockIdx.x * 128; wr0 = 1536;
    }
    const int m0 = blockIdx.y * 128;

    const int tid  = threadIdx.x;
    const int lane = tid & 31;
    const int w    = tid >> 5;
    const int wm   = w & 1;
    const int wn   = w >> 1;
    const int tq   = lane >> 2;
    const int tr   = lane & 3;

    const int lrow = tid >> 1;
    const int lw   = (tid & 1) * 4;

    const size_t aoff = (size_t)(m0 + lrow) * 512 + lw;
    const size_t boff = (size_t)(wr0 + n0 + lrow) * 512 + lw;
    const int so = lrow * PSTR + lw;

    float c[16][4];
    #pragma unroll
    for (int i = 0; i < 16; i++)
        #pragma unroll
        for (int j = 0; j < 4; j++) c[i][j] = 0.f;

    *(uint4*)&Ah[0][so] = *(const uint4*)&ap[aoff];
    *(uint4*)&Am[0][so] = *(const uint4*)&amp[aoff];
    *(uint4*)&Bh[0][so] = *(const uint4*)&g_wh[boff];
    *(uint4*)&Bm[0][so] = *(const uint4*)&g_wm[boff];
    __syncthreads();

    const int niter = D / 16;
    int cur = 0;
    for (int it = 0; it < niter; it++) {
        uint4 pah, pam, pbh, pbm;
        const bool has_next = (it + 1 < niter);
        if (has_next) {
            int kw = (it + 1) * 8;
            pah = *(const uint4*)&ap[aoff + kw];
            pam = *(const uint4*)&amp[aoff + kw];
            pbh = *(const uint4*)&g_wh[boff + kw];
            pbm = *(const uint4*)&g_wm[boff + kw];
        }

        const uint32_t* ah = Ah[cur]; const uint32_t* am = Am[cur];
        const uint32_t* bh = Bh[cur]; const uint32_t* bm = Bm[cur];

        uint32_t afh[4][4], afm[4][4], bfh[4][2], bfm[4][2];
        #pragma unroll
        for (int mi = 0; mi < 4; mi++) {
            int r = wm * 64 + mi * 16 + tq;
            afh[mi][0] = ah[r*PSTR + tr];     afh[mi][1] = ah[(r+8)*PSTR + tr];
            afh[mi][2] = ah[r*PSTR + tr + 4]; afh[mi][3] = ah[(r+8)*PSTR + tr + 4];
            afm[mi][0] = am[r*PSTR + tr];     afm[mi][1] = am[(r+8)*PSTR + tr];
            afm[mi][2] = am[r*PSTR + tr + 4]; afm[mi][3] = am[(r+8)*PSTR + tr + 4];
        }
        #pragma unroll
        for (int ni = 0; ni < 4; ni++) {
            int rn = wn * 32 + ni * 8 + tq;
            bfh[ni][0] = bh[rn*PSTR + tr]; bfh[ni][1] = bh[rn*PSTR + tr + 4];
            bfm[ni][0] = bm[rn*PSTR + tr]; bfm[ni][1] = bm[rn*PSTR + tr + 4];
        }
        // pass-outer ordering: 16 independent accumulator chains per pass
        #pragma unroll
        for (int mi = 0; mi < 4; mi++)
            #pragma unroll
            for (int ni = 0; ni < 4; ni++)
                mma_bf16(c[mi*4+ni], afh[mi], bfh[ni]);
        #pragma unroll
        for (int mi = 0; mi < 4; mi++)
            #pragma unroll
            for (int ni = 0; ni < 4; ni++)
                mma_bf16(c[mi*4+ni], afh[mi], bfm[ni]);
        #pragma unroll
        for (int mi = 0; mi < 4; mi++)
            #pragma unroll
            for (int ni = 0; ni < 4; ni++)
                mma_bf16(c[mi*4+ni], afm[mi], bfh[ni]);

        if (has_next) {
            int nxt = cur ^ 1;
            *(uint4*)&Ah[nxt][so] = pah;
            *(uint4*)&Am[nxt][so] = pam;
            *(uint4*)&Bh[nxt][so] = pbh;
            *(uint4*)&Bm[nxt][so] = pbm;
            __syncthreads();
            cur = nxt;
        }
    }

    if (!vjob) {
        #pragma unroll
        for (int mi = 0; mi < 4; mi++)
            #pragma unroll
            for (int ni = 0; ni < 4; ni++) {
                int row = m0 + wm*64 + mi*16 + tq;
                int col = n0 + wn*32 + ni*8 + 2*tr;
                float* cp = c[mi*4+ni];
                *(float2*)(C + (size_t)row * N + col)       = make_float2(cp[0], cp[1]);
                *(float2*)(C + (size_t)(row + 8) * N + col) = make_float2(cp[2], cp[3]);
            }
    } else {
        const float l0 = lam[0], l1 = lam[1];
        #pragma unroll
        for (int mi = 0; mi < 4; mi++)
            #pragma unroll
            for (int ni = 0; ni < 4; ni++) {
                int row = m0 + wm*64 + mi*16 + tq;
                int col = n0 + wn*32 + ni*8 + 2*tr;
                float* cp = c[mi*4+ni];
                #pragma unroll
                for (int half = 0; half < 2; half++) {
                    size_t gi = (size_t)(row + half*8) * N + col;
                    float2 vee = *(const float2*)(ve + gi);
                    float2 v00 = *(const float2*)(v0 + gi);
                    float r0 = cp[half*2]   + vee.x;
                    float r1 = cp[half*2+1] + vee.y;
                    *(float2*)(raw_out + gi) = make_float2(r0, r1);
                    *(float2*)(g_v + gi) = make_float2(l0*v00.x + l1*r0, l0*v00.y + l1*r1);
                }
            }
    }
}

// ---------------- merged RMSNorm + RoPE (+gain), trig from table ----------------
__global__ void rmsnorm_rope_pack(const float* __restrict__ gain) {
    int grow = blockIdx.x * 8 + (threadIdx.x >> 5);
    int lane = threadIdx.x & 31;
    const bool isQ = grow < B*T*NH;
    int row = isQ ? grow : grow - B*T*NH;
    int H   = isQ ? NH : NKV;
    const float* src = isQ ? g_q : g_k;
    int t = (row / H) % T;
    int h = row % H;
    const float* p = src + (size_t)row * HD;

    float a  = p[lane];
    float b2 = p[lane + 32];
    float ss = a*a + b2*b2;
    #pragma unroll
    for (int o = 16; o; o >>= 1) ss += __shfl_xor_sync(0xffffffffu, ss, o);
    float r = rsqrtf(ss * (1.0f/HD) + EPSF);
    a *= r; b2 *= r;

    float cc = g_ct[t * 32 + lane];
    float sn = g_st[t * 32 + lane];

    float o1 =  a*cc + b2*sn;
    float o2 = -a*sn + b2*cc;
    if (isQ) { float gg = gain[h]; o1 *= gg; o2 *= gg; }

    float p1 = __shfl_xor_sync(0xffffffffu, o1, 1);
    float p2 = __shfl_xor_sync(0xffffffffu, o2, 1);
    uint32_t wh, wmv; int widx;
    if (lane & 1) { split2_pack_f16(p2, o2, wh, wmv); widx = 16 + (lane >> 1); }
    else          { split2_pack_f16(o1, p1, wh, wmv); widx = lane >> 1; }
    if (isQ) {
        g_qh[(size_t)row * 32 + widx] = wh;
    } else {
        int pidx = (widx & 7)*4 + (widx >> 3);
        g_kh[(size_t)row * 32 + pidx] = wh;
        g_km[(size_t)row * 32 + pidx] = wmv;
    }
}

// ---------------- V pack ----------------
__global__ void v_pack() {
    int idx = blockIdx.x * 256 + threadIdx.x;
    int d  = idx & 63;
    int tp = (idx >> 6) & (T/2 - 1);
    int kv = (idx >> 16) & 3;
    int b  = idx >> 18;
    float a  = g_v[((size_t)(b*T + 2*tp)     * NKV + kv) * HD + d];
    float b2 = g_v[((size_t)(b*T + 2*tp + 1) * NKV + kv) * HD + d];
    uint32_t wh, wmv;
    split2_pack_f16(a, b2, wh, wmv);
    size_t vb = ((size_t)(b*NKV + kv) * (T/2) + tp) * 64;
    int pd = (d & 7)*8 + (d >> 3);
    g_vth[vb + pd] = wh;
    g_vtm[vb + pd] = wmv;
}

// ---------------- gate ----------------
__global__ void gate_kernel(const float* __restrict__ x, const float* __restrict__ gw,
                            const float* __restrict__ gb) {
    __shared__ float xs[D];
    int bt = blockIdx.x;
    for (int i = threadIdx.x; i < D; i += 512) xs[i] = x[(size_t)bt * D + i];
    __syncthreads();
    int h = threadIdx.x >> 5, lane = threadIdx.x & 31;
    const float* w = gw + (size_t)h * D;
    float s = 0.f;
    for (int i = lane; i < D; i += 32) s += xs[i] * w[i];
    #pragma unroll
    for (int o = 16; o; o >>= 1) s += __shfl_xor_sync(0xffffffffu, s, o);
    if (lane == 0) g_gate[bt * NH + h] = 1.0f / (1.0f + __expf(-(s + gb[h])));
}

// ---------------- fp16 flash attention: ILP-ordered MMAs ----------------
__global__ __launch_bounds__(128)
void attn_f16() {
    __shared__ uint32_t Kh[64*KSTR], Km[64*KSTR];
    __shared__ uint32_t Vh[32*VSTR], Vm[32*VSTR];

    const int qt = (int)gridDim.x - 1 - (int)blockIdx.x;
    const int h = blockIdx.y, b = blockIdx.z;
    const int kv = h / GQ;
    const int tid = threadIdx.x;
    const int w = tid >> 5, lane = tid & 31;
    const int tq = lane >> 2, tr = lane & 3;
    const int r0 = w * 16 + tq;

    uint32_t qh[4][4];
    {
        const size_t qA = ((size_t)(b*T + qt*64 + r0) * NH + h) * 32;
        const size_t qB = qA + (size_t)8 * NH * 32;
        #pragma unroll
        for (int kb = 0; kb < 4; kb++) {
            qh[kb][0] = g_qh[qA + kb*8 + tr];     qh[kb][1] = g_qh[qB + kb*8 + tr];
            qh[kb][2] = g_qh[qA + kb*8 + tr + 4]; qh[kb][3] = g_qh[qB + kb*8 + tr + 4];
        }
    }

    float o[8][4];
    #pragma unroll
    for (int ni = 0; ni < 8; ni++)
        #pragma unroll
        for (int j = 0; j < 4; j++) o[ni][j] = 0.f;
    float m0r = -1e30f, m1r = -1e30f, l0r = 0.f, l1r = 0.f;

    const size_t kbase = ((size_t)(b*T) * NKV + kv) * 32;
    const size_t vbase = ((size_t)(b*NKV + kv)) * (T/2) * 64;
    const uint32_t ONES = 0x3C003C00u;
    uint32_t bones[2] = {ONES, ONES};

    for (int kt = 0; kt <= qt; kt++) {
        const int t0 = kt * 64;
        __syncthreads();
        #pragma unroll
        for (int ci = 0; ci < 4; ci++) {
            int i = tid + ci * 128;
            int r = i >> 3, j = (i & 7) * 4;
            size_t src = kbase + (size_t)(t0 + r) * (NKV*32) + j;
            *(uint4*)&Kh[r*KSTR + j] = *(const uint4*)&g_kh[src];
            *(uint4*)&Km[r*KSTR + j] = *(const uint4*)&g_km[src];
        }
        #pragma unroll
        for (int ci = 0; ci < 4; ci++) {
            int i = tid + ci * 128;
            int tp = i >> 4, j = (i & 15) * 4;
            size_t src = vbase + (size_t)(t0/2 + tp) * 64 + j;
            *(uint4*)&Vh[tp*VSTR + j] = *(const uint4*)&g_vth[src];
            *(uint4*)&Vm[tp*VSTR + j] = *(const uint4*)&g_vtm[src];
        }
        __syncthreads();

        // ---- S = Q@K^T, ni in groups of 4 for 4-way ILP (per-acc order preserved) ----
        float s[8][4];
        #pragma unroll
        for (int ng = 0; ng < 2; ng++) {
            uint4 fh0[4], fh1[4], fm0[4], fm1[4];
            #pragma unroll
            for (int j = 0; j < 4; j++) {
                int ni = ng*4 + j;
                s[ni][0] = s[ni][1] = s[ni][2] = s[ni][3] = 0.f;
                const int kn = (ni*8 + tq) * KSTR;
                fh0[j] = *(const uint4*)&Kh[kn + tr*4];
                fh1[j] = *(const uint4*)&Kh[kn + tr*4 + 16];
                fm0[j] = *(const uint4*)&Km[kn + tr*4];
                fm1[j] = *(const uint4*)&Km[kn + tr*4 + 16];
            }
            #pragma unroll
            for (int kb = 0; kb < 4; kb++) {
                #pragma unroll
                for (int j = 0; j < 4; j++) {
                    uint32_t bh[2];
                    bh[0] = (kb==0)?fh0[j].x:(kb==1)?fh0[j].y:(kb==2)?fh0[j].z:fh0[j].w;
                    bh[1] = (kb==0)?fh1[j].x:(kb==1)?fh1[j].y:(kb==2)?fh1[j].z:fh1[j].w;
                    mma_f16(s[ng*4+j], qh[kb], bh);
                }
                #pragma unroll
                for (int j = 0; j < 4; j++) {
                    uint32_t bm[2];
                    bm[0] = (kb==0)?fm0[j].x:(kb==1)?fm0[j].y:(kb==2)?fm0[j].z:fm0[j].w;
                    bm[1] = (kb==0)?fm1[j].x:(kb==1)?fm1[j].y:(kb==2)?fm1[j].z:fm1[j].w;
                    mma_f16(s[ng*4+j], qh[kb], bm);
                }
            }
        }

        // ---- causal mask (diagonal tile only) ----
        const int rowa = qt*64 + r0, rowb = rowa + 8;
        if (kt == qt) {
            #pragma unroll
            for (int ni = 0; ni < 8; ni++) {
                int col = t0 + ni*8 + 2*tr;
                if (col     > rowa) s[ni][0] = -1e30f;
                if (col + 1 > rowa) s[ni][1] = -1e30f;
                if (col     > rowb) s[ni][2] = -1e30f;
                if (col + 1 > rowb) s[ni][3] = -1e30f;
            }
        }

        // ---- online softmax ----
        const float SC = 0.125f;
        float mx0 = -1e30f, mx1 = -1e30f;
        #pragma unroll
        for (int ni = 0; ni < 8; ni++) {
            mx0 = fmaxf(mx0, fmaxf(s[ni][0], s[ni][1]));
            mx1 = fmaxf(mx1, fmaxf(s[ni][2], s[ni][3]));
        }
        mx0 = fmaxf(mx0, __shfl_xor_sync(0xffffffffu, mx0, 1));
        mx0 = fmaxf(mx0, __shfl_xor_sync(0xffffffffu, mx0, 2));
        mx1 = fmaxf(mx1, __shfl_xor_sync(0xffffffffu, mx1, 1));
        mx1 = fmaxf(mx1, __shfl_xor_sync(0xffffffffu, mx1, 2));
        float mn0 = fmaxf(m0r, mx0 * SC);
        float mn1 = fmaxf(m1r, mx1 * SC);
        float al0 = exp2f((m0r - mn0) * LOG2E);
        float al1 = exp2f((m1r - mn1) * LOG2E);
        m0r = mn0; m1r = mn1;

        const float cf = SC * LOG2E;
        const float d0 = mn0 * LOG2E;
        const float d1 = mn1 * LOG2E;
        uint32_t pw[8][2];
        #pragma unroll
        for (int ni = 0; ni < 8; ni++) {
            pw[ni][0] = ex2_pair(fmaf(s[ni][0], cf, -d0), fmaf(s[ni][1], cf, -d0));
            pw[ni][1] = ex2_pair(fmaf(s[ni][2], cf, -d1), fmaf(s[ni][3], cf, -d1));
            o[ni][0] *= al0; o[ni][1] *= al0; o[ni][2] *= al1; o[ni][3] *= al1;
        }

        // ---- O += P@V, l += P@ones: vh pass then vm pass (8-way ILP) ----
        float lacc[4] = {0.f, 0.f, 0.f, 0.f};
        #pragma unroll
        for (int c0 = 0; c0 < 4; c0++) {
            uint32_t ph[4] = {pw[2*c0][0], pw[2*c0][1], pw[2*c0+1][0], pw[2*c0+1][1]};
            mma_f16(lacc, ph, bones);
            const int ra = (c0*8 + tr) * VSTR + tq*8;
            const int rb = (c0*8 + tr + 4) * VSTR + tq*8;
            uint4 hA0 = *(const uint4*)&Vh[ra];
            uint4 hA1 = *(const uint4*)&Vh[ra + 4];
            uint4 hB0 = *(const uint4*)&Vh[rb];
            uint4 hB1 = *(const uint4*)&Vh[rb + 4];
            uint4 mA0 = *(const uint4*)&Vm[ra];
            uint4 mA1 = *(const uint4*)&Vm[ra + 4];
            uint4 mB0 = *(const uint4*)&Vm[rb];
            uint4 mB1 = *(const uint4*)&Vm[rb + 4];
            uint32_t v2[2];
            // vh pass: 8 independent MMAs
            v2[0]=hA0.x; v2[1]=hB0.x; mma_f16(o[0], ph, v2);
            v2[0]=hA0.y; v2[1]=hB0.y; mma_f16(o[1], ph, v2);
            v2[0]=hA0.z; v2[1]=hB0.z; mma_f16(o[2], ph, v2);
            v2[0]=hA0.w; v2[1]=hB0.w; mma_f16(o[3], ph, v2);
            v2[0]=hA1.x; v2[1]=hB1.x; mma_f16(o[4], ph, v2);
            v2[0]=hA1.y; v2[1]=hB1.y; mma_f16(o[5], ph, v2);
            v2[0]=hA1.z; v2[1]=hB1.z; mma_f16(o[6], ph, v2);
            v2[0]=hA1.w; v2[1]=hB1.w; mma_f16(o[7], ph, v2);
            // vm pass: 8 independent MMAs
            v2[0]=mA0.x; v2[1]=mB0.x; mma_f16(o[0], ph, v2);
            v2[0]=mA0.y; v2[1]=mB0.y; mma_f16(o[1], ph, v2);
            v2[0]=mA0.z; v2[1]=mB0.z; mma_f16(o[2], ph, v2);
            v2[0]=mA0.w; v2[1]=mB0.w; mma_f16(o[3], ph, v2);
            v2[0]=mA1.x; v2[1]=mB1.x; mma_f16(o[4], ph, v2);
            v2[0]=mA1.y; v2[1]=mB1.y; mma_f16(o[5], ph, v2);
            v2[0]=mA1.z; v2[1]=mB1.z; mma_f16(o[6], ph, v2);
            v2[0]=mA1.w; v2[1]=mB1.w; mma_f16(o[7], ph, v2);
        }
        l0r = l0r * al0 + lacc[0];
        l1r = l1r * al1 + lacc[2];
    }

    // ---- epilogue ----
    const int rowa = qt*64 + r0, rowb = rowa + 8;
    float g0 = g_gate[(b*T + rowa) * NH + h] / l0r;
    float g1 = g_gate[(b*T + rowb) * NH + h] / l1r;
    #pragma unroll
    for (int ni = 0; ni < 8; ni++) {
        int col = ni*8 + 2*tr;
        size_t ba = ((size_t)(b*T + rowa) * NH + h) * HD + col;
        size_t bb = ((size_t)(b*T + rowb) * NH + h) * HD + col;
        *(float2*)(g_y + ba) = make_float2(o[ni][0] * g0, o[ni][1] * g0);
        *(float2*)(g_y + bb) = make_float2(o[ni][2] * g1, o[ni][3] * g1);
    }
}

// ---------------- launch ----------------
extern "C" void kernel_launch(void* const* d_in, const int* in_sizes, int n_in,
                              void* d_out, int out_size) {
    (void)in_sizes; (void)n_in; (void)out_size;
    const float* x  = (const float*)d_in[0];
    const float* qw = (const float*)d_in[1];
    const float* kw = (const float*)d_in[2];
    const float* vw = (const float*)d_in[3];
    const float* ow = (const float*)d_in[4];
    const float* ve = (const float*)d_in[5];
    const float* v0 = (const float*)d_in[6];
    const float* qg = (const float*)d_in[7];
    const float* vl = (const float*)d_in[8];
    const float* gw = (const float*)d_in[9];
    const float* gb = (const float*)d_in[10];

    float* out     = (float*)d_out;
    float* raw_out = out + (size_t)B * T * D;

    const double nb = 10000.0 * pow((double)T / 1024.0, 64.0 / 62.0);

    split_in<<<(XWORDS + WWORDS + 255) / 256, 256>>>(x, qw, kw, vw, ow);
    trig_table<<<(T*32)/256, 256>>>(nb);
    gemm_bf16<<<dim3(12, (B*T)/128), 256>>>(ve, v0, vl, nullptr, raw_out, 0);
    rmsnorm_rope_pack<<<(B*T*(NH+NKV))/8, 256>>>(qg);
    v_pack<<<(B*NKV*(T/2)*HD)/256, 256>>>();
    gate_kernel<<<B*T, 512>>>(x, gw, gb);
    attn_f16<<<dim3(T/64, NH, B), 128>>>();
    split_y<<<XWORDS/256, 256>>>();
    gemm_bf16<<<dim3(D/128, (B*T)/128), 256>>>(nullptr, nullptr, nullptr, out, nullptr, 1);
}